// round 1
// baseline (speedup 1.0000x reference)
#include <cuda_runtime.h>
#include <cstddef>

#define N_NODES  100000
#define N_EDGES  1000000
#define DIM      64
#define N_GRAPHS 2048

// ---------------- scratch (device globals; no allocation allowed) ----------
__device__ float g_h  [N_NODES * DIM];   // current node features
__device__ float g_t  [N_NODES * DIM];   // h @ W_l  (message term, pre-aggregation)
__device__ float g_r  [N_NODES * DIM];   // h @ W_r + b (self term)
__device__ float g_agg[N_NODES * DIM];   // scatter-add accumulator
__device__ float g_rinv[N_NODES];        // 1/max(deg,1); also used as deg counter
__device__ float g_pool[N_GRAPHS * DIM]; // graph sums
__device__ float g_gcnt[N_GRAPHS];       // graph node counts

// sm_90+ vectorized global reduction (4 floats per op)
__device__ __forceinline__ void red4(float* p, float4 v) {
    asm volatile("red.global.add.v4.f32 [%0], {%1,%2,%3,%4};"
                 :: "l"(p), "f"(v.x), "f"(v.y), "f"(v.z), "f"(v.w) : "memory");
}

// ---------------- zero kernels --------------------------------------------
__global__ void k_zero_agg() {
    int idx = blockIdx.x * blockDim.x + threadIdx.x;   // N_NODES*16 float4s
    if (idx < N_NODES * (DIM / 4))
        reinterpret_cast<float4*>(g_agg)[idx] = make_float4(0.f, 0.f, 0.f, 0.f);
}

__global__ void k_zero_stats() {
    int i = blockIdx.x * blockDim.x + threadIdx.x;     // covers max(131072, N)
    if (i < N_NODES)        g_rinv[i] = 0.f;
    if (i < N_GRAPHS * DIM) g_pool[i] = 0.f;
    if (i < N_GRAPHS)       g_gcnt[i] = 0.f;
}

// ---------------- degree ---------------------------------------------------
__global__ void k_degree(const int* __restrict__ dst) {
    int e = blockIdx.x * blockDim.x + threadIdx.x;
    if (e < N_EDGES) atomicAdd(&g_rinv[dst[e]], 1.0f);
}

__global__ void k_rinv() {
    int i = blockIdx.x * blockDim.x + threadIdx.x;
    if (i < N_NODES) g_rinv[i] = 1.0f / fmaxf(g_rinv[i], 1.0f);
}

// ---------------- fused dual matmul:  t = h@Wl ;  r = h@Wr + b -------------
// One thread per node. h-row (64 floats) lives in registers; Wl|Wr packed
// into a 64x128 smem tile read as broadcast float4s.
// For layer 1, hin = emb and xidx selects the embedding row.
// For layer 2, hin == nullptr -> read g_h directly.
__global__ __launch_bounds__(128) void k_transform(
    const float* __restrict__ hin, const int* __restrict__ xidx,
    const float* __restrict__ Wl, const float* __restrict__ Wr,
    const float* __restrict__ b)
{
    __shared__ float Ws[DIM * 128];   // [k][j]; j<64 -> Wl, j>=64 -> Wr
    __shared__ float bs[DIM];
    int tid = threadIdx.x;
    for (int idx = tid; idx < DIM * DIM; idx += 128) {
        int row = idx >> 6, col = idx & 63;
        Ws[row * 128 + col]      = Wl[idx];
        Ws[row * 128 + 64 + col] = Wr[idx];
    }
    if (tid < DIM) bs[tid] = b[tid];
    __syncthreads();

    int i = blockIdx.x * 128 + tid;
    if (i >= N_NODES) return;

    const float* hrow = hin ? (hin + (size_t)xidx[i] * DIM)
                            : (g_h + (size_t)i * DIM);
    float hv[DIM];
    #pragma unroll
    for (int k = 0; k < DIM / 4; k++) {
        float4 v = __ldg(reinterpret_cast<const float4*>(hrow) + k);
        hv[4 * k + 0] = v.x; hv[4 * k + 1] = v.y;
        hv[4 * k + 2] = v.z; hv[4 * k + 3] = v.w;
    }

    const float4* Ws4 = reinterpret_cast<const float4*>(Ws);
    float4* tout = reinterpret_cast<float4*>(g_t + (size_t)i * DIM);
    float4* rout = reinterpret_cast<float4*>(g_r + (size_t)i * DIM);

    for (int jt = 0; jt < 32; jt++) {                 // rolled: keeps I$ small
        float4 acc = make_float4(0.f, 0.f, 0.f, 0.f);
        #pragma unroll
        for (int k = 0; k < DIM; k++) {               // unrolled: hv stays in regs
            float4 w = Ws4[k * 32 + jt];
            float hk = hv[k];
            acc.x += hk * w.x; acc.y += hk * w.y;
            acc.z += hk * w.z; acc.w += hk * w.w;
        }
        if (jt < 16) {
            tout[jt] = acc;
        } else {
            int j4 = jt - 16;
            acc.x += bs[4 * j4 + 0]; acc.y += bs[4 * j4 + 1];
            acc.z += bs[4 * j4 + 2]; acc.w += bs[4 * j4 + 3];
            rout[j4] = acc;
        }
    }
}

// ---------------- edge scatter:  agg[dst] += t[src] ------------------------
// 4 threads per edge; each moves 16 floats via 4x (LDG.128 + red.v4).
__global__ void k_edge(const int* __restrict__ src, const int* __restrict__ dst) {
    int idx = blockIdx.x * blockDim.x + threadIdx.x;
    if (idx >= N_EDGES * 4) return;
    int e = idx >> 2, q = idx & 3;
    int s = __ldg(src + e);
    int d = __ldg(dst + e);
    const float4* tp = reinterpret_cast<const float4*>(g_t + (size_t)s * DIM) + q * 4;
    float*        ap = g_agg + (size_t)d * DIM + q * 16;
    float4 v0 = __ldg(tp + 0), v1 = __ldg(tp + 1);
    float4 v2 = __ldg(tp + 2), v3 = __ldg(tp + 3);
    red4(ap +  0, v0); red4(ap +  4, v1);
    red4(ap +  8, v2); red4(ap + 12, v3);
}

// ---------------- node epilogue:  h = relu(agg*rinv + r) -------------------
__global__ void k_node() {
    int idx = blockIdx.x * blockDim.x + threadIdx.x;   // N_NODES*16 float4s
    if (idx >= N_NODES * (DIM / 4)) return;
    int i = idx >> 4;
    float s  = g_rinv[i];
    float4 a = reinterpret_cast<const float4*>(g_agg)[idx];
    float4 r = reinterpret_cast<const float4*>(g_r)[idx];
    float4 h;
    h.x = fmaxf(a.x * s + r.x, 0.f);
    h.y = fmaxf(a.y * s + r.y, 0.f);
    h.z = fmaxf(a.z * s + r.z, 0.f);
    h.w = fmaxf(a.w * s + r.w, 0.f);
    reinterpret_cast<float4*>(g_h)[idx] = h;
}

// ---------------- global mean pool (sums + counts) -------------------------
__global__ void k_pool(const int* __restrict__ batch) {
    int idx = blockIdx.x * blockDim.x + threadIdx.x;   // N_NODES*16 float4s
    if (idx >= N_NODES * (DIM / 4)) return;
    int i = idx >> 4;
    int g = __ldg(batch + i);
    float4 v = reinterpret_cast<const float4*>(g_h)[idx];
    red4(&g_pool[(size_t)g * DIM + (idx & 15) * 4], v);
}

__global__ void k_gcnt(const int* __restrict__ batch) {
    int i = blockIdx.x * blockDim.x + threadIdx.x;
    if (i < N_NODES) atomicAdd(&g_gcnt[batch[i]], 1.0f);
}

// ---------------- classifier:  out = (pool/gcnt) @ Wout + bout -------------
// One warp per graph.
__global__ void k_out(const float* __restrict__ Wout, const float* __restrict__ bout,
                      float* __restrict__ out) {
    int gid  = (blockIdx.x * blockDim.x + threadIdx.x) >> 5;
    int lane = threadIdx.x & 31;
    if (gid >= N_GRAPHS) return;
    float inv = 1.0f / fmaxf(g_gcnt[gid], 1.0f);
    float p0 = 0.f, p1 = 0.f;
    #pragma unroll
    for (int t = 0; t < 2; t++) {
        int j = lane * 2 + t;
        float v = g_pool[(size_t)gid * DIM + j] * inv;
        p0 += v * __ldg(Wout + j * 2 + 0);
        p1 += v * __ldg(Wout + j * 2 + 1);
    }
    #pragma unroll
    for (int off = 16; off; off >>= 1) {
        p0 += __shfl_down_sync(0xFFFFFFFFu, p0, off);
        p1 += __shfl_down_sync(0xFFFFFFFFu, p1, off);
    }
    if (lane == 0) {
        out[gid * 2 + 0] = p0 + __ldg(bout + 0);
        out[gid * 2 + 1] = p1 + __ldg(bout + 1);
    }
}

// ---------------- launch ---------------------------------------------------
extern "C" void kernel_launch(void* const* d_in, const int* in_sizes, int n_in,
                              void* d_out, int out_size) {
    const int*   x     = (const int*)  d_in[0];
    const int*   ei    = (const int*)  d_in[1];   // [2, E] row-major
    const int*   batch = (const int*)  d_in[2];
    const float* emb   = (const float*)d_in[3];
    const float* W1l   = (const float*)d_in[4];
    const float* b1    = (const float*)d_in[5];
    const float* W1r   = (const float*)d_in[6];
    const float* W2l   = (const float*)d_in[7];
    const float* b2    = (const float*)d_in[8];
    const float* W2r   = (const float*)d_in[9];
    const float* Wout  = (const float*)d_in[10];
    const float* bout  = (const float*)d_in[11];
    float* out = (float*)d_out;

    const int* src = ei;
    const int* dst = ei + N_EDGES;

    const int ZSTATS = (N_GRAPHS * DIM > N_NODES) ? N_GRAPHS * DIM : N_NODES;
    const int NV4    = N_NODES * (DIM / 4);

    k_zero_stats<<<(ZSTATS + 255) / 256, 256>>>();
    k_degree    <<<(N_EDGES + 255) / 256, 256>>>(dst);
    k_rinv      <<<(N_NODES + 255) / 256, 256>>>();

    // layer 1
    k_transform <<<(N_NODES + 127) / 128, 128>>>(emb, x, W1l, W1r, b1);
    k_zero_agg  <<<(NV4 + 255) / 256, 256>>>();
    k_edge      <<<(N_EDGES * 4 + 255) / 256, 256>>>(src, dst);
    k_node      <<<(NV4 + 255) / 256, 256>>>();

    // layer 2
    k_transform <<<(N_NODES + 127) / 128, 128>>>(nullptr, nullptr, W2l, W2r, b2);
    k_zero_agg  <<<(NV4 + 255) / 256, 256>>>();
    k_edge      <<<(N_EDGES * 4 + 255) / 256, 256>>>(src, dst);
    k_node      <<<(NV4 + 255) / 256, 256>>>();

    // pool + classifier
    k_pool      <<<(NV4 + 255) / 256, 256>>>(batch);
    k_gcnt      <<<(N_NODES + 255) / 256, 256>>>(batch);
    k_out       <<<(N_GRAPHS * 32 + 255) / 256, 256>>>(Wout, bout, out);
}